// round 15
// baseline (speedup 1.0000x reference)
#include <cuda_runtime.h>
#include <cuda_fp16.h>
#include <mma.h>
#include <math.h>
#include <stdint.h>

using namespace nvcuda;

// 0: x [1024,2560]  1: h [1024,2560,16]  2: W_dt_low [160,2560]  3: W_dt [2560,160]
// 4: b_dt [2560]    5: W_B [16,2560]     6: W_C [16,2560]        7: A_log [2560,16]
// 8: D [2560]       out: y [1024,2560]   all f32

#define B_SZ    1024
#define DIN     2560
#define DST     16
#define DTR     160
#define NPROJ   192
#define KPAD    192
#define SPLITK  8
#define KSPLIT  (DIN / SPLITK)   // 320
#define KC      64
#define PADK    72

// h total = 1024*2560*16 floats = 10,485,760 float4. Split exactly in half.
#define PF_F4_PER_CTA 40960u            // 128 CTAs x 40960 f4 = 5,242,880 f4 = 83.9 MB
#define PF1_BASE_F4   (128u * PF_F4_PER_CTA)   // 5,242,880

// ---------------- device scratch ----------------
__device__ __align__(16) __half g_xh[B_SZ * DIN], g_xl[B_SZ * DIN];
__device__ __align__(16) __half g_w1[NPROJ * DIN];
__device__ __align__(16) __half g_w2[DIN * KPAD];
__device__ __align__(16) __half g_ph[B_SZ * KPAD], g_pl[B_SZ * KPAD];
__device__ __align__(16) float g_partial[SPLITK * B_SZ * NPROJ];
__device__ __align__(16) float g_proj[B_SZ * NPROJ];
__device__ __align__(16) float g_dt[B_SZ * DIN];
__device__ __align__(16) float g_A2[DIN * DST];
__device__ float g_sink[256];

// ---------------- helpers ----------------
__device__ __forceinline__ void split2h(float v, __half& hi, __half& lo) {
    hi = __float2half_rn(v);
    lo = __float2half_rn(v - __half2float(hi));
}
__device__ __forceinline__ void split_store4h(float4 v, __half* ph, __half* pl) {
    __half h0, h1, h2, h3, l0, l1, l2, l3;
    split2h(v.x, h0, l0); split2h(v.y, h1, l1); split2h(v.z, h2, l2); split2h(v.w, h3, l3);
    reinterpret_cast<__half2*>(ph)[0] = __halves2half2(h0, h1);
    reinterpret_cast<__half2*>(ph)[1] = __halves2half2(h2, h3);
    reinterpret_cast<__half2*>(pl)[0] = __halves2half2(l0, l1);
    reinterpret_cast<__half2*>(pl)[1] = __halves2half2(l2, l3);
}
__device__ __forceinline__ void store4h(float4 v, __half* p) {
    reinterpret_cast<__half2*>(p)[0] = __halves2half2(__float2half_rn(v.x), __float2half_rn(v.y));
    reinterpret_cast<__half2*>(p)[1] = __halves2half2(__float2half_rn(v.z), __float2half_rn(v.w));
}
__device__ __forceinline__ void cp16(void* sdst, const void* gsrc) {
    asm volatile("cp.async.cg.shared.global [%0], [%1], 16;"
        :: "r"((uint32_t)__cvta_generic_to_shared(sdst)), "l"(gsrc));
}
#define CP_COMMIT() asm volatile("cp.async.commit_group;" ::: "memory")
#define CP_WAIT(N)  asm volatile("cp.async.wait_group %0;" :: "n"(N) : "memory")

// stream a slice of h through L2; sink prevents DCE.
__device__ __forceinline__ void l2_prefetch_h(const float* __restrict__ hmat,
                                              size_t base_f4, unsigned count_f4, int slot) {
    const float4* p = reinterpret_cast<const float4*>(hmat) + base_f4;
    float s = 0.f;
    for (unsigned i = threadIdx.x; i < count_f4; i += 256) {
        float4 v = __ldg(p + i);
        s += v.x + v.y + v.z + v.w;
    }
    if (s == 1234567.25f) g_sink[slot] = s;
}

// ---------------- fused prep ----------------
#define PREP_BLOCKS 3560
__global__ __launch_bounds__(256) void prep_all(const float* __restrict__ x,
                                                const float* __restrict__ wdtlow,
                                                const float* __restrict__ wb,
                                                const float* __restrict__ wc,
                                                const float* __restrict__ wdt,
                                                const float* __restrict__ alog) {
    const int bid = blockIdx.x;
    const int tid = threadIdx.x;
    if (bid < 2560) {
        int i = bid * 256 + tid;
        float4 v = reinterpret_cast<const float4*>(x)[i];
        split_store4h(v, g_xh + i * 4, g_xl + i * 4);
    } else if (bid < 3040) {
        int i = (bid - 2560) * 256 + tid;
        int n = i / (DIN / 4);
        int j = i % (DIN / 4);
        const float* row = (n < DTR) ? wdtlow + (size_t)n * DIN
                         : (n < DTR + DST) ? wb + (size_t)(n - DTR) * DIN
                         : wc + (size_t)(n - DTR - DST) * DIN;
        float4 v = reinterpret_cast<const float4*>(row)[j];
        store4h(v, g_w1 + i * 4);
    } else if (bid < 3520) {
        int i = (bid - 3040) * 256 + tid;
        int n = i / (KPAD / 4);
        int c4 = (i % (KPAD / 4)) * 4;
        float4 v = (c4 < DTR) ? *reinterpret_cast<const float4*>(wdt + (size_t)n * DTR + c4)
                              : make_float4(0.f, 0.f, 0.f, 0.f);
        store4h(v, g_w2 + (size_t)n * KPAD + c4);
    } else {
        int i = (bid - 3520) * 256 + tid;
        float4 v = reinterpret_cast<const float4*>(alog)[i];
        float4 o = make_float4(-__expf(v.x), -__expf(v.y), -__expf(v.z), -__expf(v.w));
        reinterpret_cast<float4*>(g_A2)[i] = o;
    }
}

// ---------------- wmma GEMM (R12 config) + piggyback h prefetch ----------------
#define STAGE_SZ 27648
#define SMEM_DYN (2 * STAGE_SZ)

typedef wmma::fragment<wmma::matrix_a, 16, 16, 16, __half, wmma::row_major> FragA;
typedef wmma::fragment<wmma::matrix_b, 16, 16, 16, __half, wmma::col_major> FragB;
typedef wmma::fragment<wmma::accumulator, 16, 16, 16, float> FragC;

// MODE 0 grid: (16, 3+1, SPLITK) -> y==3 rows prefetch h first half (16*8=128 CTAs)
// MODE 1 grid: (16, 40+8)        -> y>=40 rows prefetch h second half (128 CTAs)
template<int MODE>
__global__ __launch_bounds__(256, 2) void gemm_wmma(const float* __restrict__ bias,
                                                    const float* __restrict__ hmat) {
    extern __shared__ __align__(16) char smbuf[];

    if (MODE == 0 && blockIdx.y == 3) {
        int id = blockIdx.x + blockIdx.z * 16;                 // 0..127
        l2_prefetch_h(hmat, (size_t)id * PF_F4_PER_CTA, PF_F4_PER_CTA, id);
        return;
    }
    if (MODE == 1 && blockIdx.y >= 40) {
        int id = blockIdx.x + (blockIdx.y - 40) * 16;          // 0..127
        l2_prefetch_h(hmat, PF1_BASE_F4 + (size_t)id * PF_F4_PER_CTA, PF_F4_PER_CTA, 128 + id);
        return;
    }

    const int tid = threadIdx.x;
    const int wid = tid >> 5;
    const int wm = wid >> 1;
    const int wn = wid & 1;
    const int mBase = blockIdx.x * 64;
    const int nBase = blockIdx.y * 64;
    const int kOff  = (MODE == 0) ? blockIdx.z * KSPLIT : 0;
    const int nch   = ((MODE == 0) ? KSPLIT : KPAD) / KC;
    const int lda   = (MODE == 0) ? DIN : KPAD;
    const int ldb   = (MODE == 0) ? DIN : KPAD;
    const __half* aH = (MODE == 0) ? g_xh : g_ph;
    const __half* aL = (MODE == 0) ? g_xl : g_pl;
    const __half* bW = (MODE == 0) ? g_w1 : g_w2;

    auto prefetch = [&](int stage, int k0) {
        char* base = smbuf + stage * STAGE_SZ;
        __half* sAh = reinterpret_cast<__half*>(base);
        __half* sAl = reinterpret_cast<__half*>(base + 9216);
        __half* sB  = reinterpret_cast<__half*>(base + 18432);
#pragma unroll
        for (int s = 0; s < 2; s++) {
            int u = tid + s * 256;
            int row = u >> 3, c16 = u & 7;
            const size_t goa = (size_t)(mBase + row) * lda + k0 + c16 * 8;
            const size_t gob = (size_t)(nBase + row) * ldb + k0 + c16 * 8;
            cp16(sAh + row * PADK + c16 * 8, aH + goa);
            cp16(sAl + row * PADK + c16 * 8, aL + goa);
            cp16(sB  + row * PADK + c16 * 8, bW + gob);
        }
        CP_COMMIT();
    };

    FragC acc0[2], acc1[2];
#pragma unroll
    for (int j = 0; j < 2; j++) { wmma::fill_fragment(acc0[j], 0.0f); wmma::fill_fragment(acc1[j], 0.0f); }

    prefetch(0, kOff);

    FragA ah[2], al[2];
    FragB bf[2][2];

    for (int ch = 0; ch < nch; ch++) {
        const int stage = ch & 1;
        if (ch + 1 < nch) {
            prefetch(stage ^ 1, kOff + (ch + 1) * KC);
            CP_WAIT(1);
        } else {
            CP_WAIT(0);
        }
        __syncthreads();

        char* base = smbuf + stage * STAGE_SZ;
        __half* sAh = reinterpret_cast<__half*>(base);
        __half* sAl = reinterpret_cast<__half*>(base + 9216);
        __half* sB  = reinterpret_cast<__half*>(base + 18432);

        wmma::load_matrix_sync(ah[0], sAh + (wm * 16) * PADK, PADK);
        wmma::load_matrix_sync(al[0], sAl + (wm * 16) * PADK, PADK);
#pragma unroll
        for (int j = 0; j < 2; j++)
            wmma::load_matrix_sync(bf[0][j], sB + (wn * 32 + j * 16) * PADK, PADK);

#pragma unroll
        for (int kk = 0; kk < 4; kk++) {
            const int cur = kk & 1, nxt = cur ^ 1;
            if (kk < 3) {
                wmma::load_matrix_sync(ah[nxt], sAh + (wm * 16) * PADK + (kk + 1) * 16, PADK);
                wmma::load_matrix_sync(al[nxt], sAl + (wm * 16) * PADK + (kk + 1) * 16, PADK);
#pragma unroll
                for (int j = 0; j < 2; j++)
                    wmma::load_matrix_sync(bf[nxt][j], sB + (wn * 32 + j * 16) * PADK + (kk + 1) * 16, PADK);
            }
            wmma::mma_sync(acc0[0], ah[cur], bf[cur][0], acc0[0]);
            wmma::mma_sync(acc0[1], ah[cur], bf[cur][1], acc0[1]);
            wmma::mma_sync(acc1[0], al[cur], bf[cur][0], acc1[0]);
            wmma::mma_sync(acc1[1], al[cur], bf[cur][1], acc1[1]);
        }
        __syncthreads();
    }

    FragC acc[2];
#pragma unroll
    for (int j = 0; j < 2; j++) {
#pragma unroll
        for (int e = 0; e < acc[j].num_elements; e++)
            acc[j].x[e] = acc0[j].x[e] + acc1[j].x[e];
    }

    if (MODE == 0) {
        float* base = g_partial + ((size_t)blockIdx.z * B_SZ + mBase) * NPROJ + nBase;
#pragma unroll
        for (int j = 0; j < 2; j++) {
            float* p = base + (size_t)(wm * 16) * NPROJ + wn * 32 + j * 16;
            wmma::store_matrix_sync(p, acc[j], NPROJ, wmma::mem_row_major);
        }
    } else {
        float* stage = reinterpret_cast<float*>(smbuf);
#pragma unroll
        for (int j = 0; j < 2; j++) {
            float* p = stage + (size_t)(wm * 16) * 68 + wn * 32 + j * 16;
            wmma::store_matrix_sync(p, acc[j], 68, wmma::mem_row_major);
        }
        __syncthreads();
#pragma unroll
        for (int s = 0; s < 4; s++) {
            int u = tid + s * 256;
            int row = u >> 4, c4 = (u & 15) * 4;
            float4 v = *reinterpret_cast<float4*>(stage + row * 68 + c4);
            const int gn = nBase + c4;
            v.x += __ldg(bias + gn);     v.y += __ldg(bias + gn + 1);
            v.z += __ldg(bias + gn + 2); v.w += __ldg(bias + gn + 3);
            float4 o;
            o.x = fmaxf(v.x, 0.f) + log1pf(__expf(-fabsf(v.x)));
            o.y = fmaxf(v.y, 0.f) + log1pf(__expf(-fabsf(v.y)));
            o.z = fmaxf(v.z, 0.f) + log1pf(__expf(-fabsf(v.z)));
            o.w = fmaxf(v.w, 0.f) + log1pf(__expf(-fabsf(v.w)));
            *reinterpret_cast<float4*>(g_dt + (size_t)(mBase + row) * DIN + gn) = o;
        }
    }
}

// ---------------- split-K reduce + fp16 split of proj ----------------
__global__ void reduce_kernel() {
    int i = blockIdx.x * blockDim.x + threadIdx.x;
    const int total = B_SZ * NPROJ;
    if (i >= total) return;
    float s = g_partial[i];
#pragma unroll
    for (int z = 1; z < SPLITK; z++) s += g_partial[(size_t)z * total + i];
    g_proj[i] = s;
    __half hi, lo;
    split2h(s, hi, lo);
    g_ph[i] = hi; g_pl[i] = lo;
}

// ---------------- elementwise SSM ----------------
__global__ __launch_bounds__(256) void ssm_kernel(const float* __restrict__ x,
                                                  const float* __restrict__ h,
                                                  const float* __restrict__ Dv,
                                                  float* __restrict__ y) {
    __shared__ float ys[64];
    const int b = blockIdx.y;
    const int dBase = blockIdx.x * 64;
    const int tid = threadIdx.x;
    const int l4 = tid & 3;
    const int d = dBase + (tid >> 2);
    const int pair = b * DIN + d;

    const float dt_v = g_dt[pair];
    const float x_v = x[pair];
    const float4 h4  = *reinterpret_cast<const float4*>(h + (size_t)pair * DST + l4 * 4);
    const float4 A4  = *reinterpret_cast<const float4*>(g_A2 + (size_t)d * DST + l4 * 4);
    const float4 Bt4 = *reinterpret_cast<const float4*>(g_proj + (size_t)b * NPROJ + DTR + l4 * 4);
    const float4 Ct4 = *reinterpret_cast<const float4*>(g_proj + (size_t)b * NPROJ + DTR + DST + l4 * 4);

    const float dx = dt_v * x_v;
    float acc;
    {
        float e0 = __expf(dt_v * A4.x);
        float e1 = __expf(dt_v * A4.y);
        float e2 = __expf(dt_v * A4.z);
        float e3 = __expf(dt_v * A4.w);
        float hn0 = fmaf(e0, h4.x, dx * Bt4.x);
        float hn1 = fmaf(e1, h4.y, dx * Bt4.y);
        float hn2 = fmaf(e2, h4.z, dx * Bt4.z);
        float hn3 = fmaf(e3, h4.w, dx * Bt4.w);
        acc = hn0 * Ct4.x;
        acc = fmaf(hn1, Ct4.y, acc);
        acc = fmaf(hn2, Ct4.z, acc);
        acc = fmaf(hn3, Ct4.w, acc);
    }
    acc += __shfl_xor_sync(0xffffffffu, acc, 1);
    acc += __shfl_xor_sync(0xffffffffu, acc, 2);
    if (l4 == 0) ys[tid >> 2] = fmaf(Dv[d], x_v, acc);
    __syncthreads();
    if (tid < 64) y[(size_t)b * DIN + dBase + tid] = ys[tid];
}

// ---------------- launch ----------------
extern "C" void kernel_launch(void* const* d_in, const int* in_sizes, int n_in,
                              void* d_out, int out_size) {
    const float* x      = (const float*)d_in[0];
    const float* h      = (const float*)d_in[1];
    const float* wdtlow = (const float*)d_in[2];
    const float* wdt    = (const float*)d_in[3];
    const float* bdt    = (const float*)d_in[4];
    const float* wb     = (const float*)d_in[5];
    const float* wc     = (const float*)d_in[6];
    const float* alog   = (const float*)d_in[7];
    const float* Dv     = (const float*)d_in[8];
    float* y = (float*)d_out;

    cudaFuncSetAttribute(gemm_wmma<0>, cudaFuncAttributeMaxDynamicSharedMemorySize, SMEM_DYN);
    cudaFuncSetAttribute(gemm_wmma<1>, cudaFuncAttributeMaxDynamicSharedMemorySize, SMEM_DYN);

    prep_all<<<PREP_BLOCKS, 256>>>(x, wdtlow, wb, wc, wdt, alog);
    gemm_wmma<0><<<dim3(B_SZ / 64, NPROJ / 64 + 1, SPLITK), 256, SMEM_DYN>>>(bdt, h);
    reduce_kernel<<<(B_SZ * NPROJ + 255) / 256, 256>>>();
    gemm_wmma<1><<<dim3(B_SZ / 64, DIN / 64 + 8, 1), 256, SMEM_DYN>>>(bdt, h);
    ssm_kernel<<<dim3(DIN / 64, B_SZ), 256>>>(x, h, Dv, y);
}

// round 16
// speedup vs baseline: 1.8089x; 1.8089x over previous
#include <cuda_runtime.h>
#include <cuda_fp16.h>
#include <mma.h>
#include <math.h>
#include <stdint.h>

using namespace nvcuda;

// 0: x [1024,2560]  1: h [1024,2560,16]  2: W_dt_low [160,2560]  3: W_dt [2560,160]
// 4: b_dt [2560]    5: W_B [16,2560]     6: W_C [16,2560]        7: A_log [2560,16]
// 8: D [2560]       out: y [1024,2560]   all f32

#define B_SZ    1024
#define DIN     2560
#define DST     16
#define DTR     160
#define NPROJ   192
#define KPAD    192      // storage stride of proj/w2 arrays (only first 160 cols used by gemm1)
#define SPLITK  8
#define KSPLIT  (DIN / SPLITK)   // 320

// ---------------- device scratch ----------------
__device__ __align__(16) __half g_xh[B_SZ * DIN], g_xl[B_SZ * DIN];
__device__ __align__(16) __half g_w1[NPROJ * DIN];
__device__ __align__(16) __half g_w2[DIN * KPAD];
__device__ __align__(16) __half g_ph[B_SZ * KPAD], g_pl[B_SZ * KPAD];
__device__ __align__(16) float g_partial[SPLITK * B_SZ * NPROJ];
__device__ __align__(16) float g_proj[B_SZ * NPROJ];
__device__ __align__(16) float g_dt[B_SZ * DIN];
__device__ __align__(16) float g_A2[DIN * DST];

// ---------------- helpers ----------------
__device__ __forceinline__ void split2h(float v, __half& hi, __half& lo) {
    hi = __float2half_rn(v);
    lo = __float2half_rn(v - __half2float(hi));
}
__device__ __forceinline__ void split_store4h(float4 v, __half* ph, __half* pl) {
    __half h0, h1, h2, h3, l0, l1, l2, l3;
    split2h(v.x, h0, l0); split2h(v.y, h1, l1); split2h(v.z, h2, l2); split2h(v.w, h3, l3);
    reinterpret_cast<__half2*>(ph)[0] = __halves2half2(h0, h1);
    reinterpret_cast<__half2*>(ph)[1] = __halves2half2(h2, h3);
    reinterpret_cast<__half2*>(pl)[0] = __halves2half2(l0, l1);
    reinterpret_cast<__half2*>(pl)[1] = __halves2half2(l2, l3);
}
__device__ __forceinline__ void store4h(float4 v, __half* p) {
    reinterpret_cast<__half2*>(p)[0] = __halves2half2(__float2half_rn(v.x), __float2half_rn(v.y));
    reinterpret_cast<__half2*>(p)[1] = __halves2half2(__float2half_rn(v.z), __float2half_rn(v.w));
}
__device__ __forceinline__ void cp16(void* sdst, const void* gsrc) {
    asm volatile("cp.async.cg.shared.global [%0], [%1], 16;"
        :: "r"((uint32_t)__cvta_generic_to_shared(sdst)), "l"(gsrc));
}
#define CP_COMMIT() asm volatile("cp.async.commit_group;" ::: "memory")
#define CP_WAIT(N)  asm volatile("cp.async.wait_group %0;" :: "n"(N) : "memory")

// ---------------- fused prep ----------------
#define PREP_BLOCKS 3560
__global__ __launch_bounds__(256) void prep_all(const float* __restrict__ x,
                                                const float* __restrict__ wdtlow,
                                                const float* __restrict__ wb,
                                                const float* __restrict__ wc,
                                                const float* __restrict__ wdt,
                                                const float* __restrict__ alog) {
    const int bid = blockIdx.x;
    const int tid = threadIdx.x;
    if (bid < 2560) {
        int i = bid * 256 + tid;
        float4 v = reinterpret_cast<const float4*>(x)[i];
        split_store4h(v, g_xh + i * 4, g_xl + i * 4);
    } else if (bid < 3040) {
        int i = (bid - 2560) * 256 + tid;
        int n = i / (DIN / 4);
        int j = i % (DIN / 4);
        const float* row = (n < DTR) ? wdtlow + (size_t)n * DIN
                         : (n < DTR + DST) ? wb + (size_t)(n - DTR) * DIN
                         : wc + (size_t)(n - DTR - DST) * DIN;
        float4 v = reinterpret_cast<const float4*>(row)[j];
        store4h(v, g_w1 + i * 4);
    } else if (bid < 3520) {
        int i = (bid - 3040) * 256 + tid;
        int n = i / (KPAD / 4);
        int c4 = (i % (KPAD / 4)) * 4;
        float4 v = (c4 < DTR) ? *reinterpret_cast<const float4*>(wdt + (size_t)n * DTR + c4)
                              : make_float4(0.f, 0.f, 0.f, 0.f);
        store4h(v, g_w2 + (size_t)n * KPAD + c4);
    } else {
        int i = (bid - 3520) * 256 + tid;
        float4 v = reinterpret_cast<const float4*>(alog)[i];
        float4 o = make_float4(-__expf(v.x), -__expf(v.y), -__expf(v.z), -__expf(v.w));
        reinterpret_cast<float4*>(g_A2)[i] = o;
    }
}

// ---------------- wmma GEMM, 64m x 64n CTA, 8 warps (4x2), warp = 16m x 32n ----------------
// fp16, A split hi/lo (2 terms), B single; cp.async 2-stage; register-pipelined fragments.
// MODE 0: KC=64 (4 kk), PADK=72, stage 27648. MODE 1: KC=32 (2 kk), PADK=40, stage 15360, K=160.
template<int MODE> struct GCfg;
template<> struct GCfg<0> { static const int KC = 64, PADK = 72, STG = 27648, KTOT = KSPLIT; };
template<> struct GCfg<1> { static const int KC = 32, PADK = 40, STG = 15360, KTOT = DTR; };

#define SMEM_DYN0 (2 * 27648)
#define SMEM_DYN1 (2 * 15360 + 17408)  // stages + dt staging (64x68 f32) headroom
// (dt staging reuses stage memory; total dyn must cover max(2*STG, 17408))

typedef wmma::fragment<wmma::matrix_a, 16, 16, 16, __half, wmma::row_major> FragA;
typedef wmma::fragment<wmma::matrix_b, 16, 16, 16, __half, wmma::col_major> FragB;
typedef wmma::fragment<wmma::accumulator, 16, 16, 16, float> FragC;

template<int MODE>
__global__ __launch_bounds__(256, 2) void gemm_wmma(const float* __restrict__ bias) {
    extern __shared__ __align__(16) char smbuf[];
    const int KC = GCfg<MODE>::KC;
    const int PADK = GCfg<MODE>::PADK;
    const int STG = GCfg<MODE>::STG;
    const int KSEG = STG / 3;            // bytes per A/B sub-buffer
    const int NKK = KC / 16;

    const int tid = threadIdx.x;
    const int wid = tid >> 5;
    const int wm = wid >> 1;
    const int wn = wid & 1;
    const int mBase = blockIdx.x * 64;
    const int nBase = blockIdx.y * 64;
    const int kOff  = (MODE == 0) ? blockIdx.z * KSPLIT : 0;
    const int nch   = GCfg<MODE>::KTOT / KC;
    const int lda   = (MODE == 0) ? DIN : KPAD;
    const int ldb   = (MODE == 0) ? DIN : KPAD;
    const __half* aH = (MODE == 0) ? g_xh : g_ph;
    const __half* aL = (MODE == 0) ? g_xl : g_pl;
    const __half* bW = (MODE == 0) ? g_w1 : g_w2;

    auto prefetch = [&](int stage, int k0) {
        char* base = smbuf + stage * STG;
        __half* sAh = reinterpret_cast<__half*>(base);
        __half* sAl = reinterpret_cast<__half*>(base + KSEG);
        __half* sB  = reinterpret_cast<__half*>(base + 2 * KSEG);
        // 64 rows x (KC/8) c16 units per matrix
        const int nc16 = KC / 8;                       // 8 or 4
        const int total = 64 * nc16;                   // 512 or 256
        for (int u = tid; u < total; u += 256) {
            int row = u / nc16, c16 = u % nc16;
            const size_t goa = (size_t)(mBase + row) * lda + k0 + c16 * 8;
            const size_t gob = (size_t)(nBase + row) * ldb + k0 + c16 * 8;
            cp16(sAh + row * PADK + c16 * 8, aH + goa);
            cp16(sAl + row * PADK + c16 * 8, aL + goa);
            cp16(sB  + row * PADK + c16 * 8, bW + gob);
        }
        CP_COMMIT();
    };

    FragC acc0[2], acc1[2];
#pragma unroll
    for (int j = 0; j < 2; j++) { wmma::fill_fragment(acc0[j], 0.0f); wmma::fill_fragment(acc1[j], 0.0f); }

    prefetch(0, kOff);

    for (int ch = 0; ch < nch; ch++) {
        const int stage = ch & 1;
        if (ch + 1 < nch) {
            prefetch(stage ^ 1, kOff + (ch + 1) * KC);
            CP_WAIT(1);
        } else {
            CP_WAIT(0);
        }
        __syncthreads();

        char* base = smbuf + stage * STG;
        __half* sAh = reinterpret_cast<__half*>(base);
        __half* sAl = reinterpret_cast<__half*>(base + KSEG);
        __half* sB  = reinterpret_cast<__half*>(base + 2 * KSEG);

#pragma unroll
        for (int kk = 0; kk < NKK; kk++) {
            FragA ah, al;
            FragB bf[2];
            wmma::load_matrix_sync(ah, sAh + (wm * 16) * PADK + kk * 16, PADK);
            wmma::load_matrix_sync(al, sAl + (wm * 16) * PADK + kk * 16, PADK);
#pragma unroll
            for (int j = 0; j < 2; j++)
                wmma::load_matrix_sync(bf[j], sB + (wn * 32 + j * 16) * PADK + kk * 16, PADK);
            wmma::mma_sync(acc0[0], ah, bf[0], acc0[0]);
            wmma::mma_sync(acc0[1], ah, bf[1], acc0[1]);
            wmma::mma_sync(acc1[0], al, bf[0], acc1[0]);
            wmma::mma_sync(acc1[1], al, bf[1], acc1[1]);
        }
        __syncthreads();
    }

    FragC acc[2];
#pragma unroll
    for (int j = 0; j < 2; j++) {
#pragma unroll
        for (int e = 0; e < acc[j].num_elements; e++)
            acc[j].x[e] = acc0[j].x[e] + acc1[j].x[e];
    }

    if (MODE == 0) {
        float* base = g_partial + ((size_t)blockIdx.z * B_SZ + mBase) * NPROJ + nBase;
#pragma unroll
        for (int j = 0; j < 2; j++) {
            float* p = base + (size_t)(wm * 16) * NPROJ + wn * 32 + j * 16;
            wmma::store_matrix_sync(p, acc[j], NPROJ, wmma::mem_row_major);
        }
    } else {
        float* stage = reinterpret_cast<float*>(smbuf);   // 64 x 68 f32 = 17408B
#pragma unroll
        for (int j = 0; j < 2; j++) {
            float* p = stage + (size_t)(wm * 16) * 68 + wn * 32 + j * 16;
            wmma::store_matrix_sync(p, acc[j], 68, wmma::mem_row_major);
        }
        __syncthreads();
#pragma unroll
        for (int s = 0; s < 4; s++) {
            int u = tid + s * 256;
            int row = u >> 4, c4 = (u & 15) * 4;
            float4 v = *reinterpret_cast<float4*>(stage + row * 68 + c4);
            const int gn = nBase + c4;
            v.x += __ldg(bias + gn);     v.y += __ldg(bias + gn + 1);
            v.z += __ldg(bias + gn + 2); v.w += __ldg(bias + gn + 3);
            float4 o;
            o.x = fmaxf(v.x, 0.f) + log1pf(__expf(-fabsf(v.x)));
            o.y = fmaxf(v.y, 0.f) + log1pf(__expf(-fabsf(v.y)));
            o.z = fmaxf(v.z, 0.f) + log1pf(__expf(-fabsf(v.z)));
            o.w = fmaxf(v.w, 0.f) + log1pf(__expf(-fabsf(v.w)));
            *reinterpret_cast<float4*>(g_dt + (size_t)(mBase + row) * DIN + gn) = o;
        }
    }
}

// ---------------- split-K reduce + fp16 split of proj ----------------
__global__ void reduce_kernel() {
    int i = blockIdx.x * blockDim.x + threadIdx.x;
    const int total = B_SZ * NPROJ;
    if (i >= total) return;
    float s = g_partial[i];
#pragma unroll
    for (int z = 1; z < SPLITK; z++) s += g_partial[(size_t)z * total + i];
    g_proj[i] = s;
    __half hi, lo;
    split2h(s, hi, lo);
    g_ph[i] = hi; g_pl[i] = lo;
}

// ---------------- elementwise SSM: 256 d's per block, 4 segments, front-batched loads ----------------
__global__ __launch_bounds__(256) void ssm_kernel(const float* __restrict__ x,
                                                  const float* __restrict__ h,
                                                  const float* __restrict__ Dv,
                                                  float* __restrict__ y) {
    __shared__ float ys[256];
    const int b = blockIdx.y;
    const int dBase = blockIdx.x * 256;
    const int tid = threadIdx.x;
    const int l4 = tid & 3;
    const int r  = tid >> 2;               // 0..63

    // front-batch all independent loads (MLP = 4 on h)
    float4 h4[4], A4[4];
    float dtv[4], xv[4];
#pragma unroll
    for (int seg = 0; seg < 4; seg++) {
        const int d = dBase + seg * 64 + r;
        const int pair = b * DIN + d;
        h4[seg] = *reinterpret_cast<const float4*>(h + (size_t)pair * DST + l4 * 4);
        A4[seg] = *reinterpret_cast<const float4*>(g_A2 + (size_t)d * DST + l4 * 4);
        dtv[seg] = g_dt[pair];
        xv[seg]  = x[pair];
    }
    const float4 Bt4 = *reinterpret_cast<const float4*>(g_proj + (size_t)b * NPROJ + DTR + l4 * 4);
    const float4 Ct4 = *reinterpret_cast<const float4*>(g_proj + (size_t)b * NPROJ + DTR + DST + l4 * 4);

#pragma unroll
    for (int seg = 0; seg < 4; seg++) {
        const float dt_v = dtv[seg];
        const float dx = dt_v * xv[seg];
        float e0 = __expf(dt_v * A4[seg].x);
        float e1 = __expf(dt_v * A4[seg].y);
        float e2 = __expf(dt_v * A4[seg].z);
        float e3 = __expf(dt_v * A4[seg].w);
        float hn0 = fmaf(e0, h4[seg].x, dx * Bt4.x);
        float hn1 = fmaf(e1, h4[seg].y, dx * Bt4.y);
        float hn2 = fmaf(e2, h4[seg].z, dx * Bt4.z);
        float hn3 = fmaf(e3, h4[seg].w, dx * Bt4.w);
        float acc = hn0 * Ct4.x;
        acc = fmaf(hn1, Ct4.y, acc);
        acc = fmaf(hn2, Ct4.z, acc);
        acc = fmaf(hn3, Ct4.w, acc);
        acc += __shfl_xor_sync(0xffffffffu, acc, 1);
        acc += __shfl_xor_sync(0xffffffffu, acc, 2);
        if (l4 == 0) ys[seg * 64 + r] = fmaf(__ldg(Dv + dBase + seg * 64 + r), xv[seg], acc);
    }
    __syncthreads();
    y[(size_t)b * DIN + dBase + tid] = ys[tid];
}

// ---------------- launch ----------------
extern "C" void kernel_launch(void* const* d_in, const int* in_sizes, int n_in,
                              void* d_out, int out_size) {
    const float* x      = (const float*)d_in[0];
    const float* h      = (const float*)d_in[1];
    const float* wdtlow = (const float*)d_in[2];
    const float* wdt    = (const float*)d_in[3];
    const float* bdt    = (const float*)d_in[4];
    const float* wb     = (const float*)d_in[5];
    const float* wc     = (const float*)d_in[6];
    const float* alog   = (const float*)d_in[7];
    const float* Dv     = (const float*)d_in[8];
    float* y = (float*)d_out;

    cudaFuncSetAttribute(gemm_wmma<0>, cudaFuncAttributeMaxDynamicSharedMemorySize, SMEM_DYN0);
    cudaFuncSetAttribute(gemm_wmma<1>, cudaFuncAttributeMaxDynamicSharedMemorySize, SMEM_DYN1);

    prep_all<<<PREP_BLOCKS, 256>>>(x, wdtlow, wb, wc, wdt, alog);
    gemm_wmma<0><<<dim3(B_SZ / 64, NPROJ / 64, SPLITK), 256, SMEM_DYN0>>>(bdt);
    reduce_kernel<<<(B_SZ * NPROJ + 255) / 256, 256>>>();
    gemm_wmma<1><<<dim3(B_SZ / 64, DIN / 64, 1), 256, SMEM_DYN1>>>(bdt);
    ssm_kernel<<<dim3(DIN / 256, B_SZ), 256>>>(x, h, Dv, y);
}

// round 17
// speedup vs baseline: 2.2314x; 1.2336x over previous
#include <cuda_runtime.h>
#include <cuda_fp16.h>
#include <mma.h>
#include <math.h>
#include <stdint.h>

using namespace nvcuda;

// 0: x [1024,2560]  1: h [1024,2560,16]  2: W_dt_low [160,2560]  3: W_dt [2560,160]
// 4: b_dt [2560]    5: W_B [16,2560]     6: W_C [16,2560]        7: A_log [2560,16]
// 8: D [2560]       out: y [1024,2560]   all f32

#define B_SZ    1024
#define DIN     2560
#define DST     16
#define DTR     160
#define NPROJ   192
#define KPAD    192
#define SPLITK  8
#define KSPLIT  (DIN / SPLITK)   // 320

// ---------------- device scratch ----------------
__device__ __align__(16) __half g_xh[B_SZ * DIN];                     // x fp16 (single term)
__device__ __align__(16) __half g_w1[NPROJ * DIN];
__device__ __align__(16) __half g_w2[DIN * KPAD];
__device__ __align__(16) __half g_ph[B_SZ * KPAD], g_pl[B_SZ * KPAD]; // proj hi/lo (gemm1 stays 2-term)
__device__ __align__(16) float g_partial[SPLITK * B_SZ * NPROJ];
__device__ __align__(16) float g_proj[B_SZ * NPROJ];
__device__ __align__(16) __half g_dth[B_SZ * DIN];                    // dt in fp16
__device__ __align__(16) float g_A2[DIN * DST];

// ---------------- helpers ----------------
__device__ __forceinline__ void split2h(float v, __half& hi, __half& lo) {
    hi = __float2half_rn(v);
    lo = __float2half_rn(v - __half2float(hi));
}
__device__ __forceinline__ void store4h(float4 v, __half* p) {
    reinterpret_cast<__half2*>(p)[0] = __halves2half2(__float2half_rn(v.x), __float2half_rn(v.y));
    reinterpret_cast<__half2*>(p)[1] = __halves2half2(__float2half_rn(v.z), __float2half_rn(v.w));
}
__device__ __forceinline__ void cp16(void* sdst, const void* gsrc) {
    asm volatile("cp.async.cg.shared.global [%0], [%1], 16;"
        :: "r"((uint32_t)__cvta_generic_to_shared(sdst)), "l"(gsrc));
}
#define CP_COMMIT() asm volatile("cp.async.commit_group;" ::: "memory")
#define CP_WAIT(N)  asm volatile("cp.async.wait_group %0;" :: "n"(N) : "memory")

// ---------------- fused prep ----------------
#define PREP_BLOCKS 3560
__global__ __launch_bounds__(256) void prep_all(const float* __restrict__ x,
                                                const float* __restrict__ wdtlow,
                                                const float* __restrict__ wb,
                                                const float* __restrict__ wc,
                                                const float* __restrict__ wdt,
                                                const float* __restrict__ alog) {
    const int bid = blockIdx.x;
    const int tid = threadIdx.x;
    if (bid < 2560) {
        int i = bid * 256 + tid;
        float4 v = reinterpret_cast<const float4*>(x)[i];
        store4h(v, g_xh + i * 4);
    } else if (bid < 3040) {
        int i = (bid - 2560) * 256 + tid;
        int n = i / (DIN / 4);
        int j = i % (DIN / 4);
        const float* row = (n < DTR) ? wdtlow + (size_t)n * DIN
                         : (n < DTR + DST) ? wb + (size_t)(n - DTR) * DIN
                         : wc + (size_t)(n - DTR - DST) * DIN;
        float4 v = reinterpret_cast<const float4*>(row)[j];
        store4h(v, g_w1 + i * 4);
    } else if (bid < 3520) {
        int i = (bid - 3040) * 256 + tid;
        int n = i / (KPAD / 4);
        int c4 = (i % (KPAD / 4)) * 4;
        float4 v = (c4 < DTR) ? *reinterpret_cast<const float4*>(wdt + (size_t)n * DTR + c4)
                              : make_float4(0.f, 0.f, 0.f, 0.f);
        store4h(v, g_w2 + (size_t)n * KPAD + c4);
    } else {
        int i = (bid - 3520) * 256 + tid;
        float4 v = reinterpret_cast<const float4*>(alog)[i];
        float4 o = make_float4(-__expf(v.x), -__expf(v.y), -__expf(v.z), -__expf(v.w));
        reinterpret_cast<float4*>(g_A2)[i] = o;
    }
}

typedef wmma::fragment<wmma::matrix_a, 16, 16, 16, __half, wmma::row_major> FragA;
typedef wmma::fragment<wmma::matrix_b, 16, 16, 16, __half, wmma::col_major> FragB;
typedef wmma::fragment<wmma::accumulator, 16, 16, 16, float> FragC;

// ---------------- GEMM0: single-term fp16, 64x64 CTA, KC=64, splitK -> g_partial ----------------
// stage: sA 9216 | sB 9216 = 18432; x2 = 36864
#define G0_PADK 72
#define G0_STG  18432
#define SMEM_DYN0 (2 * G0_STG)

__global__ __launch_bounds__(256, 2) void gemm0_kernel() {
    extern __shared__ __align__(16) char smbuf[];
    const int tid = threadIdx.x;
    const int wid = tid >> 5;
    const int wm = wid >> 1;
    const int wn = wid & 1;
    const int mBase = blockIdx.x * 64;
    const int nBase = blockIdx.y * 64;
    const int kOff  = blockIdx.z * KSPLIT;
    const int nch   = KSPLIT / 64;    // 5

    auto prefetch = [&](int stage, int k0) {
        char* base = smbuf + stage * G0_STG;
        __half* sA = reinterpret_cast<__half*>(base);
        __half* sB = reinterpret_cast<__half*>(base + 9216);
#pragma unroll
        for (int s = 0; s < 2; s++) {
            int u = tid + s * 256;
            int row = u >> 3, c16 = u & 7;
            cp16(sA + row * G0_PADK + c16 * 8, g_xh + (size_t)(mBase + row) * DIN + k0 + c16 * 8);
            cp16(sB + row * G0_PADK + c16 * 8, g_w1 + (size_t)(nBase + row) * DIN + k0 + c16 * 8);
        }
        CP_COMMIT();
    };

    FragC acc[2];
    wmma::fill_fragment(acc[0], 0.0f);
    wmma::fill_fragment(acc[1], 0.0f);

    prefetch(0, kOff);

    for (int ch = 0; ch < nch; ch++) {
        const int stage = ch & 1;
        if (ch + 1 < nch) {
            prefetch(stage ^ 1, kOff + (ch + 1) * 64);
            CP_WAIT(1);
        } else {
            CP_WAIT(0);
        }
        __syncthreads();

        char* base = smbuf + stage * G0_STG;
        __half* sA = reinterpret_cast<__half*>(base);
        __half* sB = reinterpret_cast<__half*>(base + 9216);

#pragma unroll
        for (int kk = 0; kk < 4; kk++) {
            FragA af;
            FragB bf[2];
            wmma::load_matrix_sync(af, sA + (wm * 16) * G0_PADK + kk * 16, G0_PADK);
#pragma unroll
            for (int j = 0; j < 2; j++)
                wmma::load_matrix_sync(bf[j], sB + (wn * 32 + j * 16) * G0_PADK + kk * 16, G0_PADK);
            wmma::mma_sync(acc[0], af, bf[0], acc[0]);
            wmma::mma_sync(acc[1], af, bf[1], acc[1]);
        }
        __syncthreads();
    }

    float* outp = g_partial + ((size_t)blockIdx.z * B_SZ + mBase) * NPROJ + nBase;
#pragma unroll
    for (int j = 0; j < 2; j++) {
        float* p = outp + (size_t)(wm * 16) * NPROJ + wn * 32 + j * 16;
        wmma::store_matrix_sync(p, acc[j], NPROJ, wmma::mem_row_major);
    }
}

// ---------------- GEMM1: 2-term (proj hi/lo), KC=32, K=160 -> softplus -> g_dth ----------------
// stage: sAh 5120 | sAl 5120 | sB 5120 = 15360; x2 = 30720 (dt staging 17408 fits)
#define G1_PADK 40
#define G1_STG  15360
#define SMEM_DYN1 (2 * G1_STG)

__global__ __launch_bounds__(256, 2) void gemm1_kernel(const float* __restrict__ bias) {
    extern __shared__ __align__(16) char smbuf[];
    const int tid = threadIdx.x;
    const int wid = tid >> 5;
    const int wm = wid >> 1;
    const int wn = wid & 1;
    const int mBase = blockIdx.x * 64;
    const int nBase = blockIdx.y * 64;
    const int nch = DTR / 32;   // 5

    auto prefetch = [&](int stage, int k0) {
        char* base = smbuf + stage * G1_STG;
        __half* sAh = reinterpret_cast<__half*>(base);
        __half* sAl = reinterpret_cast<__half*>(base + 5120);
        __half* sB  = reinterpret_cast<__half*>(base + 10240);
        // 64 rows x 4 c16 units = 256 slots per matrix; 1 per thread
        int row = tid >> 2, c16 = tid & 3;
        const size_t goa = (size_t)(mBase + row) * KPAD + k0 + c16 * 8;
        const size_t gob = (size_t)(nBase + row) * KPAD + k0 + c16 * 8;
        cp16(sAh + row * G1_PADK + c16 * 8, g_ph + goa);
        cp16(sAl + row * G1_PADK + c16 * 8, g_pl + goa);
        cp16(sB  + row * G1_PADK + c16 * 8, g_w2 + gob);
        CP_COMMIT();
    };

    FragC acc0[2], acc1[2];
#pragma unroll
    for (int j = 0; j < 2; j++) { wmma::fill_fragment(acc0[j], 0.0f); wmma::fill_fragment(acc1[j], 0.0f); }

    prefetch(0, 0);

    for (int ch = 0; ch < nch; ch++) {
        const int stage = ch & 1;
        if (ch + 1 < nch) {
            prefetch(stage ^ 1, (ch + 1) * 32);
            CP_WAIT(1);
        } else {
            CP_WAIT(0);
        }
        __syncthreads();

        char* base = smbuf + stage * G1_STG;
        __half* sAh = reinterpret_cast<__half*>(base);
        __half* sAl = reinterpret_cast<__half*>(base + 5120);
        __half* sB  = reinterpret_cast<__half*>(base + 10240);

#pragma unroll
        for (int kk = 0; kk < 2; kk++) {
            FragA ah, al;
            FragB bf[2];
            wmma::load_matrix_sync(ah, sAh + (wm * 16) * G1_PADK + kk * 16, G1_PADK);
            wmma::load_matrix_sync(al, sAl + (wm * 16) * G1_PADK + kk * 16, G1_PADK);
#pragma unroll
            for (int j = 0; j < 2; j++)
                wmma::load_matrix_sync(bf[j], sB + (wn * 32 + j * 16) * G1_PADK + kk * 16, G1_PADK);
            wmma::mma_sync(acc0[0], ah, bf[0], acc0[0]);
            wmma::mma_sync(acc0[1], ah, bf[1], acc0[1]);
            wmma::mma_sync(acc1[0], al, bf[0], acc1[0]);
            wmma::mma_sync(acc1[1], al, bf[1], acc1[1]);
        }
        __syncthreads();
    }

    FragC acc[2];
#pragma unroll
    for (int j = 0; j < 2; j++) {
#pragma unroll
        for (int e = 0; e < acc[j].num_elements; e++)
            acc[j].x[e] = acc0[j].x[e] + acc1[j].x[e];
    }

    // stage, softplus, write fp16 dt
    float* stage = reinterpret_cast<float*>(smbuf);   // 64 x 68 f32 = 17408B <= 30720
#pragma unroll
    for (int j = 0; j < 2; j++) {
        float* p = stage + (size_t)(wm * 16) * 68 + wn * 32 + j * 16;
        wmma::store_matrix_sync(p, acc[j], 68, wmma::mem_row_major);
    }
    __syncthreads();
#pragma unroll
    for (int s = 0; s < 4; s++) {
        int u = tid + s * 256;
        int row = u >> 4, c4 = (u & 15) * 4;
        float4 v = *reinterpret_cast<float4*>(stage + row * 68 + c4);
        const int gn = nBase + c4;
        v.x += __ldg(bias + gn);     v.y += __ldg(bias + gn + 1);
        v.z += __ldg(bias + gn + 2); v.w += __ldg(bias + gn + 3);
        float o0 = fmaxf(v.x, 0.f) + log1pf(__expf(-fabsf(v.x)));
        float o1 = fmaxf(v.y, 0.f) + log1pf(__expf(-fabsf(v.y)));
        float o2 = fmaxf(v.z, 0.f) + log1pf(__expf(-fabsf(v.z)));
        float o3 = fmaxf(v.w, 0.f) + log1pf(__expf(-fabsf(v.w)));
        __half2 p0 = __halves2half2(__float2half_rn(o0), __float2half_rn(o1));
        __half2 p1 = __halves2half2(__float2half_rn(o2), __float2half_rn(o3));
        uint2 pk = make_uint2(*reinterpret_cast<uint32_t*>(&p0), *reinterpret_cast<uint32_t*>(&p1));
        *reinterpret_cast<uint2*>(g_dth + (size_t)(mBase + row) * DIN + gn) = pk;
    }
}

// ---------------- split-K reduce + fp16 split of proj ----------------
__global__ void reduce_kernel() {
    int i = blockIdx.x * blockDim.x + threadIdx.x;
    const int total = B_SZ * NPROJ;
    if (i >= total) return;
    float s = g_partial[i];
#pragma unroll
    for (int z = 1; z < SPLITK; z++) s += g_partial[(size_t)z * total + i];
    g_proj[i] = s;
    __half hi, lo;
    split2h(s, hi, lo);
    g_ph[i] = hi; g_pl[i] = lo;
}

// ---------------- elementwise SSM: 256 d's per block, MLP=4, streaming loads ----------------
__global__ __launch_bounds__(256) void ssm_kernel(const float* __restrict__ x,
                                                  const float* __restrict__ h,
                                                  const float* __restrict__ Dv,
                                                  float* __restrict__ y) {
    __shared__ float ys[256];
    const int b = blockIdx.y;
    const int dBase = blockIdx.x * 256;
    const int tid = threadIdx.x;
    const int l4 = tid & 3;
    const int r  = tid >> 2;               // 0..63

    float4 h4[4], A4[4];
    float dtv[4], xv[4];
#pragma unroll
    for (int seg = 0; seg < 4; seg++) {
        const int d = dBase + seg * 64 + r;
        const int pair = b * DIN + d;
        h4[seg] = __ldcs(reinterpret_cast<const float4*>(h + (size_t)pair * DST + l4 * 4));
        A4[seg] = *reinterpret_cast<const float4*>(g_A2 + (size_t)d * DST + l4 * 4);
        dtv[seg] = __half2float(g_dth[pair]);
        xv[seg]  = __ldg(x + pair);
    }
    const float4 Bt4 = *reinterpret_cast<const float4*>(g_proj + (size_t)b * NPROJ + DTR + l4 * 4);
    const float4 Ct4 = *reinterpret_cast<const float4*>(g_proj + (size_t)b * NPROJ + DTR + DST + l4 * 4);

#pragma unroll
    for (int seg = 0; seg < 4; seg++) {
        const float dt_v = dtv[seg];
        const float dx = dt_v * xv[seg];
        float e0 = __expf(dt_v * A4[seg].x);
        float e1 = __expf(dt_v * A4[seg].y);
        float e2 = __expf(dt_v * A4[seg].z);
        float e3 = __expf(dt_v * A4[seg].w);
        float hn0 = fmaf(e0, h4[seg].x, dx * Bt4.x);
        float hn1 = fmaf(e1, h4[seg].y, dx * Bt4.y);
        float hn2 = fmaf(e2, h4[seg].z, dx * Bt4.z);
        float hn3 = fmaf(e3, h4[seg].w, dx * Bt4.w);
        float acc = hn0 * Ct4.x;
        acc = fmaf(hn1, Ct4.y, acc);
        acc = fmaf(hn2, Ct4.z, acc);
        acc = fmaf(hn3, Ct4.w, acc);
        acc += __shfl_xor_sync(0xffffffffu, acc, 1);
        acc += __shfl_xor_sync(0xffffffffu, acc, 2);
        if (l4 == 0) ys[seg * 64 + r] = fmaf(__ldg(Dv + dBase + seg * 64 + r), xv[seg], acc);
    }
    __syncthreads();
    __stcs(y + (size_t)b * DIN + dBase + tid, ys[tid]);
}

// ---------------- launch ----------------
extern "C" void kernel_launch(void* const* d_in, const int* in_sizes, int n_in,
                              void* d_out, int out_size) {
    const float* x      = (const float*)d_in[0];
    const float* h      = (const float*)d_in[1];
    const float* wdtlow = (const float*)d_in[2];
    const float* wdt    = (const float*)d_in[3];
    const float* bdt    = (const float*)d_in[4];
    const float* wb     = (const float*)d_in[5];
    const float* wc     = (const float*)d_in[6];
    const float* alog   = (const float*)d_in[7];
    const float* Dv     = (const float*)d_in[8];
    float* y = (float*)d_out;

    cudaFuncSetAttribute(gemm0_kernel, cudaFuncAttributeMaxDynamicSharedMemorySize, SMEM_DYN0);
    cudaFuncSetAttribute(gemm1_kernel, cudaFuncAttributeMaxDynamicSharedMemorySize, SMEM_DYN1);

    prep_all<<<PREP_BLOCKS, 256>>>(x, wdtlow, wb, wc, wdt, alog);
    gemm0_kernel<<<dim3(B_SZ / 64, NPROJ / 64, SPLITK), 256, SMEM_DYN0>>>();
    reduce_kernel<<<(B_SZ * NPROJ + 255) / 256, 256>>>();
    gemm1_kernel<<<dim3(B_SZ / 64, DIN / 64), 256, SMEM_DYN1>>>(bdt);
    ssm_kernel<<<dim3(DIN / 256, B_SZ), 256>>>(x, h, Dv, y);
}